// round 7
// baseline (speedup 1.0000x reference)
#include <cuda_runtime.h>
#include <math.h>

#define BSZ 256        // batch B
#define NSEQ 4096      // K*B
#define H 64
#define G4 256         // 4*H
#define ZXD 320
#define LSTM_IN 322
#define TT 50

typedef unsigned long long ull;

// packed f32x2 helpers (ptxas never auto-fuses; PTX-only path)
#define FMA2(d, a, b, c) asm("fma.rn.f32x2 %0, %1, %2, %3;" : "=l"(d) : "l"(a), "l"(b), "l"(c))
#define PACKF2(d, x, y)  asm("mov.b64 %0, {%1, %2};" : "=l"(d) : "f"(x), "f"(y))
#define UNPACKF2(x, y, d) asm("mov.b64 {%0, %1}, %2;" : "=f"(x), "=f"(y) : "l"(d))

__device__ __forceinline__ float tanhg(float x) {
    float y;
    asm("tanh.approx.f32 %0, %1;" : "=f"(y) : "f"(x));
    return y;
}
__device__ __forceinline__ float sigg(float x) {
    return fmaf(0.5f, tanhg(0.5f * x), 0.5f);
}

// scratch
__device__ float g_G0[NSEQ * G4];   // interleaved: [n][u*4 + q]
__device__ float g_h0[NSEQ * H];
__device__ float g_c0[NSEQ * H];

// ---------------------------------------------------------------------------
// Phase 1:  [G0 | h0 | c0] = zx @ [Wih[:, :320] | Wh0 | Wc0]^T  (+ biases)
// ---------------------------------------------------------------------------
__global__ __launch_bounds__(256) void phase1_kernel(
    const float* __restrict__ x, const float* __restrict__ z,
    const float* __restrict__ Wih, const float* __restrict__ Wh0,
    const float* __restrict__ Wc0,
    const float* __restrict__ bih, const float* __restrict__ bhh,
    const float* __restrict__ bh0, const float* __restrict__ bc0)
{
    __shared__ float As[16][68];
    __shared__ float Ws[16][68];
    const int tid = threadIdx.x;
    const int n0 = blockIdx.x * 64;
    const int c0 = blockIdx.y * 64;
    const int tx = tid & 15, ty = tid >> 4;
    float acc[4][4] = {};

    for (int kt = 0; kt < ZXD; kt += 16) {
        #pragma unroll
        for (int i = 0; i < 4; i++) {
            int e = tid + i * 256;
            int kk = e & 15, rr = e >> 4;
            int n = n0 + rr, m = kt + kk;
            float v = (m < H) ? z[n * H + m]
                              : x[(n & (BSZ - 1)) * 256 + (m - H)];
            As[kk][rr] = v;
        }
        #pragma unroll
        for (int i = 0; i < 4; i++) {
            int e = tid + i * 256;
            int kk = e & 15, cc = e >> 4;
            int j = c0 + cc, m = kt + kk;
            float v;
            if (j < G4)          v = Wih[j * LSTM_IN + m];
            else if (j < G4 + H) v = Wh0[(j - G4) * ZXD + m];
            else                 v = Wc0[(j - G4 - H) * ZXD + m];
            Ws[kk][cc] = v;
        }
        __syncthreads();
        #pragma unroll
        for (int kk = 0; kk < 16; kk++) {
            float a[4], b[4];
            #pragma unroll
            for (int i = 0; i < 4; i++) a[i] = As[kk][ty * 4 + i];
            #pragma unroll
            for (int j = 0; j < 4; j++) b[j] = Ws[kk][tx * 4 + j];
            #pragma unroll
            for (int i = 0; i < 4; i++)
                #pragma unroll
                for (int j = 0; j < 4; j++)
                    acc[i][j] += a[i] * b[j];
        }
        __syncthreads();
    }

    #pragma unroll
    for (int i = 0; i < 4; i++) {
        int n = n0 + ty * 4 + i;
        #pragma unroll
        for (int j = 0; j < 4; j++) {
            int col = c0 + tx * 4 + j;
            float v = acc[i][j];
            if (col < G4) {
                int u = col & 63, q = col >> 6;
                g_G0[n * G4 + u * 4 + q] = v + bih[col] + bhh[col];
            }
            else if (col < G4 + H) g_h0[n * H + (col - G4)]     = v + bh0[col - G4];
            else                   g_c0[n * H + (col - G4 - H)] = v + bc0[col - G4 - H];
        }
    }
}

// ---------------------------------------------------------------------------
// Phase 2: warp-specialized pipeline.  128 blocks x 32 seqs x 640 threads.
// warps 0-15 (R):  gates GEMM + pointwise for step i (critical path, 4/SMSP)
// warps 16-18(Hd): heads GEMM for h_{i-1}
// warp  19   (G):  GMM + LSE for h_{i-1}; decode prefetch
// One __syncthreads per step; H2 and DDE double-buffered.
// ---------------------------------------------------------------------------
#define PO_STRIDE 104

#define SM_WG   0                        // [64][256] packed Whh^T, 1KB rows
#define SM_WP   (SM_WG + 64 * 256)       // [64][96]  head weights^T, 384B rows
#define SM_H2   (SM_WP + 64 * 96)        // [2][64][32] ull (h,h) pairs
#define SM_PO   (SM_H2 + 2 * 64 * 64)    // [32][104] head outputs
#define SM_DDX  (SM_PO + 32 * PO_STRIDE) // [2][32] ull (dx,dx)
#define SM_DDY  (SM_DDX + 128)           // [2][32] ull (dy,dy)
#define SM_TOT  (SM_DDY + 128)
#define SMEM_BYTES (SM_TOT * 4)

#define NTH 640

__global__ __launch_bounds__(NTH, 1) void phase2_kernel(
    const float* __restrict__ inp_seqs, const float* __restrict__ pred_seqs,
    const float* __restrict__ Whh, const float* __restrict__ Wih,
    const float* __restrict__ Wpi, const float* __restrict__ bpi,
    const float* __restrict__ Wmu, const float* __restrict__ bmu,
    const float* __restrict__ Wls, const float* __restrict__ bls,
    const float* __restrict__ Wcorr, const float* __restrict__ bcorr,
    float* __restrict__ out)
{
    extern __shared__ float sm[];
    char* smb = (char*)sm;
    const int tid  = threadIdx.x;
    const int lane = tid & 31;
    const int warp = tid >> 5;
    const int sg   = lane >> 2;       // 0..7 : seqs [4sg, 4sg+4)
    const int cg   = lane & 3;        // 0..3
    const int nb   = blockIdx.x * 32;

    // ---- stage weights ----
    // gates: Wg[k][col]; col = p*2+h2i, p = u*2+hh -> gate q = 2hh+h2i of unit u
    for (int e = tid; e < 64 * 256; e += NTH) {
        int k = e >> 8, col = e & 255;
        int p = col >> 1, h2i = col & 1;
        int u = p >> 1, hh = p & 1;
        sm[SM_WG + k * 256 + col] = Whh[((hh * 2 + h2i) * 64 + u) * 64 + k];
    }
    // heads: Wp[k][j]
    for (int e = tid; e < 64 * 96; e += NTH) {
        int j = e % 96, k = e / 96;
        float v;
        if (j < 16)      v = Wpi[j * 64 + k];
        else if (j < 48) v = Wmu[(j - 16) * 64 + k];
        else if (j < 80) v = Wls[(j - 48) * 64 + k];
        else             v = Wcorr[(j - 80) * 64 + k];
        sm[SM_WP + k * 96 + j] = v;
    }
    // DDE buf1 = tgt_present (used by gates at i=1), duplicated pairs
    if (tid < 64) {
        int s = tid >> 1, d = tid & 1;
        int b = (nb + s) & (BSZ - 1);
        float v = inp_seqs[(b * 8 + 7) * 24 + 20 + d];
        int base = d ? SM_DDY : SM_DDX;
        sm[base + 64 + 2 * s]     = v;
        sm[base + 64 + 2 * s + 1] = v;
    }

    // ---- R state (warps 0-15): unit u = 4*warp+cg, 4 seqs ----
    const int u0 = 4 * warp + cg;        // valid for warp<16
    const int pb = 2 * u0;               // packed-col base (2 packed cols)
    ull G0p[4][2];
    float cr[4];
    ull WdX2[2], WdY2[2];
    if (warp < 16) {
        #pragma unroll
        for (int pp = 0; pp < 2; pp++) {
            int hh = (pb + pp) & 1;
            int q0 = 2 * hh, q1 = 2 * hh + 1;
            PACKF2(WdX2[pp], Wih[(q0 * 64 + u0) * LSTM_IN + 320],
                             Wih[(q1 * 64 + u0) * LSTM_IN + 320]);
            PACKF2(WdY2[pp], Wih[(q0 * 64 + u0) * LSTM_IN + 321],
                             Wih[(q1 * 64 + u0) * LSTM_IN + 321]);
        }
        const ull* g0p = (const ull*)g_G0;
        #pragma unroll
        for (int j = 0; j < 4; j++) {
            int n = nb + 4 * sg + j;
            G0p[j][0] = g0p[n * 128 + pb];
            G0p[j][1] = g0p[n * 128 + pb + 1];
            cr[j] = g_c0[n * H + u0];
        }
        // h0 -> H2 buf0 as (h,h) pairs
        float h0a = g_h0[(nb + 4 * sg + 0) * H + u0];
        float h0b = g_h0[(nb + 4 * sg + 1) * H + u0];
        float h0c = g_h0[(nb + 4 * sg + 2) * H + u0];
        float h0d = g_h0[(nb + 4 * sg + 3) * H + u0];
        ull q0, q1, q2, q3;
        PACKF2(q0, h0a, h0a); PACKF2(q1, h0b, h0b);
        PACKF2(q2, h0c, h0c); PACKF2(q3, h0d, h0d);
        ulonglong2 v0; v0.x = q0; v0.y = q1;
        ulonglong2 v1; v1.x = q2; v1.y = q3;
        char* hw = smb + SM_H2 * 4 + u0 * 256 + sg * 32;
        *(ulonglong2*)hw = v0;
        *(ulonglong2*)(hw + 16) = v1;
    }

    // ---- Hd constants (warps 16-18): group g = 4*(warp-16)+cg, 8 outputs ----
    ull hb[4] = {0, 0, 0, 0};
    int j0 = 0;
    if (warp >= 16 && warp < 19) {
        j0 = 8 * (4 * (warp - 16) + cg);
        float bv[8];
        #pragma unroll
        for (int jj = 0; jj < 8; jj++) {
            int j = j0 + jj;
            float v;
            if (j < 16)      v = bpi[j];
            else if (j < 48) v = bmu[j - 16];
            else if (j < 80) v = bls[j - 48];
            else             v = bcorr[j - 80];
            bv[jj] = v;
        }
        PACKF2(hb[0], bv[0], bv[1]);
        PACKF2(hb[1], bv[2], bv[3]);
        PACKF2(hb[2], bv[4], bv[5]);
        PACKF2(hb[3], bv[6], bv[7]);
    }

    // ---- G state (warp 19) ----
    const int sh = lane >> 4;     // 0/1
    const int gc = lane & 15;     // component
    float lacc[16];
    #pragma unroll
    for (int it = 0; it < 16; it++) lacc[it] = 0.f;

    __syncthreads();

    for (int i = 1; i <= TT + 1; i++) {
        const int rb = (i - 1) & 1;   // h buffer to read (h_{i-1})
        const int wbuf = i & 1;       // h buffer to write (h_i)
        const int db = i & 1;         // DDE buffer holding row i-2

        // ================= R: gates + pointwise (step i) =================
        if (warp < 16 && i <= TT) {
            ull acc[4][2];
            {
                const char* ddx = smb + SM_DDX * 4 + db * 256 + sg * 32;
                const char* ddy = smb + SM_DDY * 4 + db * 256 + sg * 32;
                ulonglong2 dxa = *(const ulonglong2*)ddx;
                ulonglong2 dxb = *(const ulonglong2*)(ddx + 16);
                ulonglong2 dya = *(const ulonglong2*)ddy;
                ulonglong2 dyb = *(const ulonglong2*)(ddy + 16);
                ull dx2[4] = {dxa.x, dxa.y, dxb.x, dxb.y};
                ull dy2[4] = {dya.x, dya.y, dyb.x, dyb.y};
                #pragma unroll
                for (int j = 0; j < 4; j++)
                    #pragma unroll
                    for (int pp = 0; pp < 2; pp++) {
                        ull t0;
                        FMA2(t0, dx2[j], WdX2[pp], G0p[j][pp]);
                        FMA2(acc[j][pp], dy2[j], WdY2[pp], t0);
                    }
            }
            const char* h2p = smb + SM_H2 * 4 + rb * 16384 + sg * 32;
            const char* wgp = smb + SM_WG * 4 + pb * 8;
            #pragma unroll 8
            for (int k = 0; k < 64; k++) {
                ulonglong2 ha = *(const ulonglong2*)(h2p + k * 256);
                ulonglong2 hc = *(const ulonglong2*)(h2p + k * 256 + 16);
                ulonglong2 w  = *(const ulonglong2*)(wgp + k * 1024);
                FMA2(acc[0][0], ha.x, w.x, acc[0][0]);
                FMA2(acc[0][1], ha.x, w.y, acc[0][1]);
                FMA2(acc[1][0], ha.y, w.x, acc[1][0]);
                FMA2(acc[1][1], ha.y, w.y, acc[1][1]);
                FMA2(acc[2][0], hc.x, w.x, acc[2][0]);
                FMA2(acc[2][1], hc.x, w.y, acc[2][1]);
                FMA2(acc[3][0], hc.y, w.x, acc[3][0]);
                FMA2(acc[3][1], hc.y, w.y, acc[3][1]);
            }
            // pointwise + duplicated h store
            float hv[4];
            #pragma unroll
            for (int j = 0; j < 4; j++) {
                float gi, gf, gg, go;
                UNPACKF2(gi, gf, acc[j][0]);
                UNPACKF2(gg, go, acc[j][1]);
                float c = sigg(gf) * cr[j] + sigg(gi) * tanhg(gg);
                cr[j] = c;
                hv[j] = sigg(go) * tanhg(c);
            }
            ull q0, q1, q2, q3;
            PACKF2(q0, hv[0], hv[0]); PACKF2(q1, hv[1], hv[1]);
            PACKF2(q2, hv[2], hv[2]); PACKF2(q3, hv[3], hv[3]);
            ulonglong2 v0; v0.x = q0; v0.y = q1;
            ulonglong2 v1; v1.x = q2; v1.y = q3;
            char* hw = smb + SM_H2 * 4 + wbuf * 16384 + u0 * 256 + sg * 32;
            *(ulonglong2*)hw = v0;
            *(ulonglong2*)(hw + 16) = v1;
        }

        // ================= Hd: heads for h_{i-1} =================
        if (warp >= 16 && warp < 19 && i >= 2) {
            ull ph[4][4];
            #pragma unroll
            for (int j = 0; j < 4; j++)
                #pragma unroll
                for (int p = 0; p < 4; p++) ph[j][p] = hb[p];
            const char* h2p = smb + SM_H2 * 4 + rb * 16384 + sg * 32;
            const char* wpp = smb + SM_WP * 4 + j0 * 4;
            #pragma unroll 4
            for (int k = 0; k < 64; k++) {
                ulonglong2 ha = *(const ulonglong2*)(h2p + k * 256);
                ulonglong2 hc = *(const ulonglong2*)(h2p + k * 256 + 16);
                ulonglong2 w0 = *(const ulonglong2*)(wpp + k * 384);
                ulonglong2 w1 = *(const ulonglong2*)(wpp + k * 384 + 16);
                FMA2(ph[0][0], ha.x, w0.x, ph[0][0]);
                FMA2(ph[0][1], ha.x, w0.y, ph[0][1]);
                FMA2(ph[0][2], ha.x, w1.x, ph[0][2]);
                FMA2(ph[0][3], ha.x, w1.y, ph[0][3]);
                FMA2(ph[1][0], ha.y, w0.x, ph[1][0]);
                FMA2(ph[1][1], ha.y, w0.y, ph[1][1]);
                FMA2(ph[1][2], ha.y, w1.x, ph[1][2]);
                FMA2(ph[1][3], ha.y, w1.y, ph[1][3]);
                FMA2(ph[2][0], hc.x, w0.x, ph[2][0]);
                FMA2(ph[2][1], hc.x, w0.y, ph[2][1]);
                FMA2(ph[2][2], hc.x, w1.x, ph[2][2]);
                FMA2(ph[2][3], hc.x, w1.y, ph[2][3]);
                FMA2(ph[3][0], hc.y, w0.x, ph[3][0]);
                FMA2(ph[3][1], hc.y, w0.y, ph[3][1]);
                FMA2(ph[3][2], hc.y, w1.x, ph[3][2]);
                FMA2(ph[3][3], hc.y, w1.y, ph[3][3]);
            }
            #pragma unroll
            for (int j = 0; j < 4; j++) {
                float a, b, c, d, e, f, g, h;
                UNPACKF2(a, b, ph[j][0]);
                UNPACKF2(c, d, ph[j][1]);
                UNPACKF2(e, f, ph[j][2]);
                UNPACKF2(g, h, ph[j][3]);
                float* po = sm + SM_PO + (4 * sg + j) * PO_STRIDE + j0;
                *(float4*)po       = make_float4(a, b, c, d);
                *(float4*)(po + 4) = make_float4(e, f, g, h);
            }
        }

        // ================= G: decode prefetch (row i-1) =================
        if (warp == 19 && i <= TT) {
            int b = (nb + lane) & (BSZ - 1);
            const float* pr = pred_seqs + (b * TT + (i - 1)) * 24 + 20;
            float vx = pr[0], vy = pr[1];
            int off = ((i + 1) & 1) * 64 + 2 * lane;
            sm[SM_DDX + off]     = vx;
            sm[SM_DDX + off + 1] = vx;
            sm[SM_DDY + off]     = vy;
            sm[SM_DDY + off + 1] = vy;
        }

        // ================= Hd+G sync, then GMM for h_{i-1} =================
        if (warp >= 16 && i >= 2) {
            asm volatile("bar.sync 1, 128;" ::: "memory");
            if (warp == 19) {
                #pragma unroll 4
                for (int it = 0; it < 16; it++) {
                    int gs = it * 2 + sh;
                    float txv = sm[SM_DDX + db * 64 + 2 * gs];
                    float tyv = sm[SM_DDY + db * 64 + 2 * gs];
                    const float* pr = sm + SM_PO + gs * PO_STRIDE;
                    float pi  = pr[gc];
                    float2 mu  = *(const float2*)(pr + 16 + 2 * gc);
                    float2 lsv = *(const float2*)(pr + 48 + 2 * gc);
                    float corr = tanhg(pr[80 + gc]);
                    float ls0 = fminf(fmaxf(lsv.x, -10.f), 10.f);
                    float ls1 = fminf(fmaxf(lsv.y, -10.f), 10.f);
                    float dx = txv - mu.x, dy = tyv - mu.y;
                    float z0 = dx * __expf(-ls0);
                    float z1 = dy * __expf(-ls1);
                    float omr  = 1.f - corr * corr;
                    float quad = z0 * z0 + z1 * z1 - 2.f * corr * z0 * z1;
                    float cv = -1.8378770664093453f - (ls0 + ls1)
                               - 0.5f * __logf(omr) - 0.5f * __fdividef(quad, omr);
                    float a = pi + cv;
                    float b2 = pi;
                    float ma = a, mb = b2;
                    #pragma unroll
                    for (int xm = 1; xm < 16; xm <<= 1) {
                        ma = fmaxf(ma, __shfl_xor_sync(0xFFFFFFFFu, ma, xm));
                        mb = fmaxf(mb, __shfl_xor_sync(0xFFFFFFFFu, mb, xm));
                    }
                    float ea = __expf(a - ma);
                    float eb = __expf(b2 - mb);
                    #pragma unroll
                    for (int xm = 1; xm < 16; xm <<= 1) {
                        ea += __shfl_xor_sync(0xFFFFFFFFu, ea, xm);
                        eb += __shfl_xor_sync(0xFFFFFFFFu, eb, xm);
                    }
                    float lp = (ma + __logf(ea)) - (mb + __logf(eb));
                    lacc[it] += fminf(lp, 50.f);
                }
            }
        }

        __syncthreads();
    }

    if (warp == 19 && (lane & 15) == 0) {
        #pragma unroll
        for (int it = 0; it < 16; it++)
            out[nb + it * 2 + sh] = lacc[it];
    }
}

// ---------------------------------------------------------------------------
extern "C" void kernel_launch(void* const* d_in, const int* in_sizes, int n_in,
                              void* d_out, int out_size)
{
    const float* x      = (const float*)d_in[0];
    const float* z      = (const float*)d_in[1];
    const float* inps   = (const float*)d_in[2];
    const float* preds  = (const float*)d_in[3];
    const float* Wh0    = (const float*)d_in[4];
    const float* bh0    = (const float*)d_in[5];
    const float* Wc0    = (const float*)d_in[6];
    const float* bc0    = (const float*)d_in[7];
    const float* Wih    = (const float*)d_in[8];
    const float* Whh    = (const float*)d_in[9];
    const float* bih    = (const float*)d_in[10];
    const float* bhh    = (const float*)d_in[11];
    const float* Wpi    = (const float*)d_in[12];
    const float* bpi    = (const float*)d_in[13];
    const float* Wmu    = (const float*)d_in[14];
    const float* bmu    = (const float*)d_in[15];
    const float* Wls    = (const float*)d_in[16];
    const float* bls    = (const float*)d_in[17];
    const float* Wcorr  = (const float*)d_in[18];
    const float* bcorr  = (const float*)d_in[19];
    float* out = (float*)d_out;

    cudaFuncSetAttribute(phase2_kernel,
                         cudaFuncAttributeMaxDynamicSharedMemorySize, SMEM_BYTES);

    dim3 g1(NSEQ / 64, 384 / 64);
    phase1_kernel<<<g1, 256>>>(x, z, Wih, Wh0, Wc0, bih, bhh, bh0, bc0);

    phase2_kernel<<<NSEQ / 32, NTH, SMEM_BYTES>>>(
        inps, preds, Whh, Wih,
        Wpi, bpi, Wmu, bmu, Wls, bls, Wcorr, bcorr, out);
}

// round 8
// speedup vs baseline: 1.4710x; 1.4710x over previous
#include <cuda_runtime.h>
#include <math.h>

#define BSZ 256        // batch B
#define NSEQ 4096      // K*B
#define H 64
#define G4 256         // 4*H
#define ZXD 320
#define LSTM_IN 322
#define TT 50
#define SEQB 16        // sequences per block (2 CTAs/SM)

typedef unsigned long long ull;

// packed f32x2 helpers (ptxas never auto-fuses; PTX-only path)
#define FMA2(d, a, b, c) asm("fma.rn.f32x2 %0, %1, %2, %3;" : "=l"(d) : "l"(a), "l"(b), "l"(c))
#define PACKF2(d, x, y)  asm("mov.b64 %0, {%1, %2};" : "=l"(d) : "f"(x), "f"(y))
#define UNPACKF2(x, y, d) asm("mov.b64 {%0, %1}, %2;" : "=f"(x), "=f"(y) : "l"(d))

__device__ __forceinline__ float tanhg(float x) {
    float y;
    asm("tanh.approx.f32 %0, %1;" : "=f"(y) : "f"(x));
    return y;
}
__device__ __forceinline__ float sigg(float x) {
    return fmaf(0.5f, tanhg(0.5f * x), 0.5f);
}

// scratch
__device__ float g_G0[NSEQ * G4];   // interleaved: [n][u*4 + q]
__device__ float g_h0[NSEQ * H];
__device__ float g_c0[NSEQ * H];

// ---------------------------------------------------------------------------
// Phase 1:  [G0 | h0 | c0] = zx @ [Wih[:, :320] | Wh0 | Wc0]^T  (+ biases)
// ---------------------------------------------------------------------------
__global__ __launch_bounds__(256) void phase1_kernel(
    const float* __restrict__ x, const float* __restrict__ z,
    const float* __restrict__ Wih, const float* __restrict__ Wh0,
    const float* __restrict__ Wc0,
    const float* __restrict__ bih, const float* __restrict__ bhh,
    const float* __restrict__ bh0, const float* __restrict__ bc0)
{
    __shared__ float As[16][68];
    __shared__ float Ws[16][68];
    const int tid = threadIdx.x;
    const int n0 = blockIdx.x * 64;
    const int c0 = blockIdx.y * 64;
    const int tx = tid & 15, ty = tid >> 4;
    float acc[4][4] = {};

    for (int kt = 0; kt < ZXD; kt += 16) {
        #pragma unroll
        for (int i = 0; i < 4; i++) {
            int e = tid + i * 256;
            int kk = e & 15, rr = e >> 4;
            int n = n0 + rr, m = kt + kk;
            float v = (m < H) ? z[n * H + m]
                              : x[(n & (BSZ - 1)) * 256 + (m - H)];
            As[kk][rr] = v;
        }
        #pragma unroll
        for (int i = 0; i < 4; i++) {
            int e = tid + i * 256;
            int kk = e & 15, cc = e >> 4;
            int j = c0 + cc, m = kt + kk;
            float v;
            if (j < G4)          v = Wih[j * LSTM_IN + m];
            else if (j < G4 + H) v = Wh0[(j - G4) * ZXD + m];
            else                 v = Wc0[(j - G4 - H) * ZXD + m];
            Ws[kk][cc] = v;
        }
        __syncthreads();
        #pragma unroll
        for (int kk = 0; kk < 16; kk++) {
            float a[4], b[4];
            #pragma unroll
            for (int i = 0; i < 4; i++) a[i] = As[kk][ty * 4 + i];
            #pragma unroll
            for (int j = 0; j < 4; j++) b[j] = Ws[kk][tx * 4 + j];
            #pragma unroll
            for (int i = 0; i < 4; i++)
                #pragma unroll
                for (int j = 0; j < 4; j++)
                    acc[i][j] += a[i] * b[j];
        }
        __syncthreads();
    }

    #pragma unroll
    for (int i = 0; i < 4; i++) {
        int n = n0 + ty * 4 + i;
        #pragma unroll
        for (int j = 0; j < 4; j++) {
            int col = c0 + tx * 4 + j;
            float v = acc[i][j];
            if (col < G4) {
                int u = col & 63, q = col >> 6;
                g_G0[n * G4 + u * 4 + q] = v + bih[col] + bhh[col];
            }
            else if (col < G4 + H) g_h0[n * H + (col - G4)]     = v + bh0[col - G4];
            else                   g_c0[n * H + (col - G4 - H)] = v + bc0[col - G4 - H];
        }
    }
}

// ---------------------------------------------------------------------------
// Phase 2: 256 blocks x 16 seqs x 256 threads, 2 CTAs/SM.
// warp w (0..7) owns units [8w, 8w+8); lane = (sg = lane>>3, ug = lane&7).
// Thread: 4 seqs (4sg..4sg+3) x 1 unit (8w+ug) = 2 packed gate cols.
// All warps participate in every phase (R5 structure); 3 barriers/step.
// ---------------------------------------------------------------------------
#define PO_STRIDE 102

#define SM_WG   0                         // [64][256] packed Whh^T, 1KB rows
#define SM_WP   (SM_WG + 64 * 256)        // [64][96]  head weights^T, 384B rows
#define SM_HST  (SM_WP + 64 * 96)         // [64][16]  h transposed (float4/sg)
#define SM_PO   (SM_HST + 64 * 16)        // [16][102] head outputs
#define SM_DX   (SM_PO + 16 * PO_STRIDE)  // [16] decode/target x
#define SM_DY   (SM_DX + 16)              // [16] decode/target y
#define SM_TOT  (SM_DY + 16)
#define SMEM_BYTES (SM_TOT * 4)

#define NTH 256

__global__ __launch_bounds__(NTH, 2) void phase2_kernel(
    const float* __restrict__ inp_seqs, const float* __restrict__ pred_seqs,
    const float* __restrict__ Whh, const float* __restrict__ Wih,
    const float* __restrict__ Wpi, const float* __restrict__ bpi,
    const float* __restrict__ Wmu, const float* __restrict__ bmu,
    const float* __restrict__ Wls, const float* __restrict__ bls,
    const float* __restrict__ Wcorr, const float* __restrict__ bcorr,
    float* __restrict__ out)
{
    extern __shared__ float sm[];
    char* smb = (char*)sm;
    const int tid  = threadIdx.x;
    const int lane = tid & 31;
    const int warp = tid >> 5;        // 0..7
    const int sg   = lane >> 3;       // 0..3 : seqs [4sg, 4sg+4)
    const int ug   = lane & 7;        // 0..7
    const int nb   = blockIdx.x * SEQB;

    // ---- stage weights ----
    // gates: Wg[k][col]; col = p*2+h2i, p = u*2+hh -> gate q = 2hh+h2i of unit u
    for (int e = tid; e < 64 * 256; e += NTH) {
        int k = e >> 8, col = e & 255;
        int p = col >> 1, h2i = col & 1;
        int u = p >> 1, hh = p & 1;
        sm[SM_WG + k * 256 + col] = Whh[((hh * 2 + h2i) * 64 + u) * 64 + k];
    }
    // heads: Wp[k][j]
    for (int e = tid; e < 64 * 96; e += NTH) {
        int j = e % 96, k = e / 96;
        float v;
        if (j < 16)      v = Wpi[j * 64 + k];
        else if (j < 48) v = Wmu[(j - 16) * 64 + k];
        else if (j < 80) v = Wls[(j - 48) * 64 + k];
        else             v = Wcorr[(j - 80) * 64 + k];
        sm[SM_WP + k * 96 + j] = v;
    }

    // ---- per-thread constants ----
    const int u0 = 8 * warp + ug;       // unit
    const int pb = 2 * u0;              // packed-col base
    ull WdX2[2], WdY2[2];
    #pragma unroll
    for (int pp = 0; pp < 2; pp++) {
        int q0 = 2 * pp, q1 = 2 * pp + 1;   // hh = pp since pb even
        PACKF2(WdX2[pp], Wih[(q0 * 64 + u0) * LSTM_IN + 320],
                         Wih[(q1 * 64 + u0) * LSTM_IN + 320]);
        PACKF2(WdY2[pp], Wih[(q0 * 64 + u0) * LSTM_IN + 321],
                         Wih[(q1 * 64 + u0) * LSTM_IN + 321]);
    }
    // head bias: warps 0..5, thread = 4 seqs x 2 outputs (j0 = 16*warp + 2*ug)
    ull hb = 0;
    const int j0 = 16 * warp + 2 * ug;
    if (warp < 6) {
        float bv[2];
        #pragma unroll
        for (int jj = 0; jj < 2; jj++) {
            int j = j0 + jj;
            float v;
            if (j < 16)      v = bpi[j];
            else if (j < 48) v = bmu[j - 16];
            else if (j < 80) v = bls[j - 48];
            else             v = bcorr[j - 80];
            bv[jj] = v;
        }
        PACKF2(hb, bv[0], bv[1]);
    }

    // ---- state: 4 seqs x 1 unit ----
    ull G0p[4][2];
    float cr[4];
    {
        const ull* g0p = (const ull*)g_G0;
        #pragma unroll
        for (int j = 0; j < 4; j++) {
            int n = nb + 4 * sg + j;
            G0p[j][0] = g0p[n * 128 + pb];
            G0p[j][1] = g0p[n * 128 + pb + 1];
            cr[j] = g_c0[n * H + u0];
        }
        float4 hv;
        hv.x = g_h0[(nb + 4 * sg + 0) * H + u0];
        hv.y = g_h0[(nb + 4 * sg + 1) * H + u0];
        hv.z = g_h0[(nb + 4 * sg + 2) * H + u0];
        hv.w = g_h0[(nb + 4 * sg + 3) * H + u0];
        ((float4*)(sm + SM_HST))[u0 * 4 + sg] = hv;
    }

    const int b_mine = (nb + (tid & 15)) & (BSZ - 1);
    if (tid < 16) {
        const float* ip = inp_seqs + (b_mine * 8 + 7) * 24 + 20;
        sm[SM_DX + tid] = ip[0];
        sm[SM_DY + tid] = ip[1];
    }
    float lacc = 0.f;
    __syncthreads();

    const float4* HsT4 = (const float4*)(sm + SM_HST);
    const char* wgp = smb + SM_WG * 4 + pb * 8;
    const char* wpp = smb + SM_WP * 4 + j0 * 4;

    // GMM role: warp = 2 seqs x 16 comps
    const int sh = lane >> 4;           // 0/1
    const int gc = lane & 15;           // component
    const int gs = 2 * warp + sh;       // sequence for GMM/LSE

    for (int t = 1; t <= TT; t++) {
        // ======== phase 1: gates ========
        ull acc[4][2];
        {
            float4 dx4 = *(const float4*)(sm + SM_DX + 4 * sg);
            float4 dy4 = *(const float4*)(sm + SM_DY + 4 * sg);
            float dxa[4] = {dx4.x, dx4.y, dx4.z, dx4.w};
            float dya[4] = {dy4.x, dy4.y, dy4.z, dy4.w};
            #pragma unroll
            for (int j = 0; j < 4; j++) {
                ull dx2, dy2;
                PACKF2(dx2, dxa[j], dxa[j]);
                PACKF2(dy2, dya[j], dya[j]);
                #pragma unroll
                for (int pp = 0; pp < 2; pp++) {
                    ull tmp;
                    FMA2(tmp, dx2, WdX2[pp], G0p[j][pp]);
                    FMA2(acc[j][pp], dy2, WdY2[pp], tmp);
                }
            }
        }
        #pragma unroll 4
        for (int k = 0; k < 64; k++) {
            float4 hv = HsT4[k * 4 + sg];
            ull h2[4];
            PACKF2(h2[0], hv.x, hv.x);
            PACKF2(h2[1], hv.y, hv.y);
            PACKF2(h2[2], hv.z, hv.z);
            PACKF2(h2[3], hv.w, hv.w);
            ulonglong2 w = *(const ulonglong2*)(wgp + k * 1024);
            #pragma unroll
            for (int j = 0; j < 4; j++) {
                FMA2(acc[j][0], h2[j], w.x, acc[j][0]);
                FMA2(acc[j][1], h2[j], w.y, acc[j][1]);
            }
        }
        __syncthreads();   // HsT / DX / DY consumed

        // ======== phase 2: pointwise LSTM + h store + decode prefetch ========
        {
            float ha[4];
            #pragma unroll
            for (int j = 0; j < 4; j++) {
                float gi, gf, gg, go;
                UNPACKF2(gi, gf, acc[j][0]);
                UNPACKF2(gg, go, acc[j][1]);
                float c = sigg(gf) * cr[j] + sigg(gi) * tanhg(gg);
                cr[j] = c;
                ha[j] = sigg(go) * tanhg(c);
            }
            ((float4*)(sm + SM_HST))[u0 * 4 + sg] = make_float4(ha[0], ha[1], ha[2], ha[3]);
        }
        if (tid < 16) {
            const float* pp2 = pred_seqs + (b_mine * TT + (t - 1)) * 24 + 20;
            sm[SM_DX + tid] = pp2[0];
            sm[SM_DY + tid] = pp2[1];
        }
        __syncthreads();   // new HsT + target row (t-1) visible

        // ======== phase 3: heads (warps 0..5) ========
        if (warp < 6) {
            ull ph[4] = {hb, hb, hb, hb};
            #pragma unroll 4
            for (int k = 0; k < 64; k++) {
                float4 hv = HsT4[k * 4 + sg];
                ull h2[4];
                PACKF2(h2[0], hv.x, hv.x);
                PACKF2(h2[1], hv.y, hv.y);
                PACKF2(h2[2], hv.z, hv.z);
                PACKF2(h2[3], hv.w, hv.w);
                ull w = *(const ull*)(wpp + k * 384);
                #pragma unroll
                for (int j = 0; j < 4; j++)
                    FMA2(ph[j], h2[j], w, ph[j]);
            }
            #pragma unroll
            for (int j = 0; j < 4; j++) {
                float a, b;
                UNPACKF2(a, b, ph[j]);
                *(float2*)(sm + SM_PO + (4 * sg + j) * PO_STRIDE + j0) = make_float2(a, b);
            }
        }
        __syncthreads();   // Po visible

        // ======== phase 4: GMM + logsumexp (warp = 2 seqs x 16 comps) ========
        {
            float txv = sm[SM_DX + gs];
            float tyv = sm[SM_DY + gs];
            const float* pr = sm + SM_PO + gs * PO_STRIDE;
            float pi  = pr[gc];
            float2 mu = *(const float2*)(pr + 16 + 2 * gc);
            float2 lsv = *(const float2*)(pr + 48 + 2 * gc);
            float corr = tanhg(pr[80 + gc]);
            float ls0 = fminf(fmaxf(lsv.x, -10.f), 10.f);
            float ls1 = fminf(fmaxf(lsv.y, -10.f), 10.f);
            float dx = txv - mu.x, dy = tyv - mu.y;
            float z0 = dx * __expf(-ls0);
            float z1 = dy * __expf(-ls1);
            float omr  = 1.f - corr * corr;
            float quad = z0 * z0 + z1 * z1 - 2.f * corr * z0 * z1;
            float cv = -1.8378770664093453f - (ls0 + ls1)
                       - 0.5f * __logf(omr) - 0.5f * __fdividef(quad, omr);
            float a = pi + cv;       // for LSE(pi + comp)
            float b = pi;            // for LSE(pi)
            float ma = a, mb = b;
            #pragma unroll
            for (int xm = 1; xm < 16; xm <<= 1) {
                ma = fmaxf(ma, __shfl_xor_sync(0xFFFFFFFFu, ma, xm));
                mb = fmaxf(mb, __shfl_xor_sync(0xFFFFFFFFu, mb, xm));
            }
            float ea = __expf(a - ma);
            float eb = __expf(b - mb);
            #pragma unroll
            for (int xm = 1; xm < 16; xm <<= 1) {
                ea += __shfl_xor_sync(0xFFFFFFFFu, ea, xm);
                eb += __shfl_xor_sync(0xFFFFFFFFu, eb, xm);
            }
            float lp = (ma + __logf(ea)) - (mb + __logf(eb));
            lacc += fminf(lp, 50.f);
        }
        // no trailing barrier: next gates only reads HsT/DX/DY (also read here);
        // Po is next written after 2 barriers in the next iteration.
    }

    if ((lane & 15) == 0) out[nb + gs] = lacc;
}

// ---------------------------------------------------------------------------
extern "C" void kernel_launch(void* const* d_in, const int* in_sizes, int n_in,
                              void* d_out, int out_size)
{
    const float* x      = (const float*)d_in[0];
    const float* z      = (const float*)d_in[1];
    const float* inps   = (const float*)d_in[2];
    const float* preds  = (const float*)d_in[3];
    const float* Wh0    = (const float*)d_in[4];
    const float* bh0    = (const float*)d_in[5];
    const float* Wc0    = (const float*)d_in[6];
    const float* bc0    = (const float*)d_in[7];
    const float* Wih    = (const float*)d_in[8];
    const float* Whh    = (const float*)d_in[9];
    const float* bih    = (const float*)d_in[10];
    const float* bhh    = (const float*)d_in[11];
    const float* Wpi    = (const float*)d_in[12];
    const float* bpi    = (const float*)d_in[13];
    const float* Wmu    = (const float*)d_in[14];
    const float* bmu    = (const float*)d_in[15];
    const float* Wls    = (const float*)d_in[16];
    const float* bls    = (const float*)d_in[17];
    const float* Wcorr  = (const float*)d_in[18];
    const float* bcorr  = (const float*)d_in[19];
    float* out = (float*)d_out;

    cudaFuncSetAttribute(phase2_kernel,
                         cudaFuncAttributeMaxDynamicSharedMemorySize, SMEM_BYTES);

    dim3 g1(NSEQ / 64, 384 / 64);
    phase1_kernel<<<g1, 256>>>(x, z, Wih, Wh0, Wc0, bih, bhh, bh0, bc0);

    phase2_kernel<<<NSEQ / SEQB, NTH, SMEM_BYTES>>>(
        inps, preds, Whh, Wih,
        Wpi, bpi, Wmu, bmu, Wls, bls, Wcorr, bcorr, out);
}

// round 10
// speedup vs baseline: 2.0220x; 1.3746x over previous
#include <cuda_runtime.h>
#include <math.h>
#include <stdint.h>

#define BSZ 256        // batch B
#define NSEQ 4096      // K*B
#define H 64
#define G4 256
#define ZXD 320
#define LSTM_IN 322
#define TT 50

__device__ __forceinline__ float tanhg(float x) {
    float y;
    asm("tanh.approx.f32 %0, %1;" : "=f"(y) : "f"(x));
    return y;
}
__device__ __forceinline__ float sigg(float x) {
    return fmaf(0.5f, tanhg(0.5f * x), 0.5f);
}
__device__ __forceinline__ uint32_t f2tf(float x) {
    uint32_t r;
    asm("cvt.rna.tf32.f32 %0, %1;" : "=r"(r) : "f"(x));
    return r;
}

// m16n8k8 tf32 mma, D += A*B (D=C in place)
__device__ __forceinline__ void mma8(float* d, const uint4& a,
                                     uint32_t b0, uint32_t b1) {
    asm volatile(
        "mma.sync.aligned.m16n8k8.row.col.f32.tf32.tf32.f32 "
        "{%0,%1,%2,%3}, {%4,%5,%6,%7}, {%8,%9}, {%0,%1,%2,%3};"
        : "+f"(d[0]), "+f"(d[1]), "+f"(d[2]), "+f"(d[3])
        : "r"(a.x), "r"(a.y), "r"(a.z), "r"(a.w), "r"(b0), "r"(b1));
}

// scratch
__device__ float g_G0[NSEQ * G4];   // [n][u*4 + q]
__device__ float g_h0[NSEQ * H];
__device__ float g_c0[NSEQ * H];

// ---------------------------------------------------------------------------
// Phase 1 (unchanged):  [G0 | h0 | c0] = zx @ [Wih[:, :320] | Wh0 | Wc0]^T
// ---------------------------------------------------------------------------
__global__ __launch_bounds__(256) void phase1_kernel(
    const float* __restrict__ x, const float* __restrict__ z,
    const float* __restrict__ Wih, const float* __restrict__ Wh0,
    const float* __restrict__ Wc0,
    const float* __restrict__ bih, const float* __restrict__ bhh,
    const float* __restrict__ bh0, const float* __restrict__ bc0)
{
    __shared__ float As[16][68];
    __shared__ float Ws[16][68];
    const int tid = threadIdx.x;
    const int n0 = blockIdx.x * 64;
    const int c0 = blockIdx.y * 64;
    const int tx = tid & 15, ty = tid >> 4;
    float acc[4][4] = {};

    for (int kt = 0; kt < ZXD; kt += 16) {
        #pragma unroll
        for (int i = 0; i < 4; i++) {
            int e = tid + i * 256;
            int kk = e & 15, rr = e >> 4;
            int n = n0 + rr, m = kt + kk;
            float v = (m < H) ? z[n * H + m]
                              : x[(n & (BSZ - 1)) * 256 + (m - H)];
            As[kk][rr] = v;
        }
        #pragma unroll
        for (int i = 0; i < 4; i++) {
            int e = tid + i * 256;
            int kk = e & 15, cc = e >> 4;
            int j = c0 + cc, m = kt + kk;
            float v;
            if (j < G4)          v = Wih[j * LSTM_IN + m];
            else if (j < G4 + H) v = Wh0[(j - G4) * ZXD + m];
            else                 v = Wc0[(j - G4 - H) * ZXD + m];
            Ws[kk][cc] = v;
        }
        __syncthreads();
        #pragma unroll
        for (int kk = 0; kk < 16; kk++) {
            float a[4], b[4];
            #pragma unroll
            for (int i = 0; i < 4; i++) a[i] = As[kk][ty * 4 + i];
            #pragma unroll
            for (int j = 0; j < 4; j++) b[j] = Ws[kk][tx * 4 + j];
            #pragma unroll
            for (int i = 0; i < 4; i++)
                #pragma unroll
                for (int j = 0; j < 4; j++)
                    acc[i][j] += a[i] * b[j];
        }
        __syncthreads();
    }

    #pragma unroll
    for (int i = 0; i < 4; i++) {
        int n = n0 + ty * 4 + i;
        #pragma unroll
        for (int j = 0; j < 4; j++) {
            int col = c0 + tx * 4 + j;
            float v = acc[i][j];
            if (col < G4) {
                int u = col & 63, q = col >> 6;
                g_G0[n * G4 + u * 4 + q] = v + bih[col] + bhh[col];
            }
            else if (col < G4 + H) g_h0[n * H + (col - G4)]     = v + bh0[col - G4];
            else                   g_c0[n * H + (col - G4 - H)] = v + bc0[col - G4 - H];
        }
    }
}

// ---------------------------------------------------------------------------
// Phase 2: mma.sync tf32 recurrence. 128 blocks x 32 seqs x 256 threads.
// A[32 x 72]: rows=seqs, cols 0-63 h, 64 dx, 65 dy, 66 one, 67-71 zero.
//   Stored fragment-major (hi and lo separately).
// B gates [256 x 72] (Wd folded at k=64/65), split hi+lo, fragment-major,
//   gate-column permutation: col j=8*(4w+i)+2m+b <-> unit 8w+2m+(i>>1),
//   gate q=2*(i&1)+b. B heads [96 x 72] (bias at k=66), single tf32.
// Per step: 3-term gates MMA -> pointwise (regs) -> h hi/lo store ->
//   heads MMA -> GMM+LSE. 3 barriers/step.
// ---------------------------------------------------------------------------
#define SM_BG   0                       // 32nt*9kt*32*4 = 36864 f (hi0,hi1,lo0,lo1)
#define SM_BHD  36864                   // 12nt*9kt*32*2 = 6912 f
#define SM_AH   43776                   // 9kt*2mt*32*4 = 2304 f
#define SM_AL   46080                   // 2304 f
#define SM_PO   48384                   // 32*100 = 3200 f
#define SM_DT   51584                   // 64 f
#define SM_TOT  51648
#define SMEM_BYTES (SM_TOT * 4)
#define NTH 256

__global__ __launch_bounds__(NTH, 1) void phase2_kernel(
    const float* __restrict__ inp_seqs, const float* __restrict__ pred_seqs,
    const float* __restrict__ Whh, const float* __restrict__ Wih,
    const float* __restrict__ Wpi, const float* __restrict__ bpi,
    const float* __restrict__ Wmu, const float* __restrict__ bmu,
    const float* __restrict__ Wls, const float* __restrict__ bls,
    const float* __restrict__ Wcorr, const float* __restrict__ bcorr,
    float* __restrict__ out)
{
    extern __shared__ float sm[];
    uint32_t* smu = (uint32_t*)sm;
    const int tid  = threadIdx.x;
    const int lane = tid & 31;
    const int warp = tid >> 5;        // 0..7
    const int nb   = blockIdx.x * 32;
    const int m4   = lane & 3;        // frag col group
    const int sr   = lane >> 2;       // frag row base

    // ---- zero A fragment region ----
    for (int e = tid; e < 4608; e += NTH) sm[SM_AH + e] = 0.f;

    // ---- stage B gates (hi+lo, fragment-major, permuted cols) ----
    for (int e = tid; e < 256 * 72; e += NTH) {
        int j = e / 72, k = e % 72;
        int w = j >> 5, i = (j >> 3) & 3, m = (j >> 1) & 3, b = j & 1;
        int u = 8 * w + 2 * m + (i >> 1);
        int q = 2 * (i & 1) + b;
        int row = q * 64 + u;
        float v = 0.f;
        if (k < 64)       v = Whh[row * 64 + k];
        else if (k == 64) v = Wih[row * LSTM_IN + 320];
        else if (k == 65) v = Wih[row * LSTM_IN + 321];
        uint32_t hi = f2tf(v);
        uint32_t lo = f2tf(v - __uint_as_float(hi));
        int nt = j >> 3, kt = k >> 3, kl = k & 7;
        int lanep = (j & 7) * 4 + (kl & 3);
        int r = kl >> 2;
        uint32_t* bp = smu + SM_BG + ((nt * 9 + kt) * 32 + lanep) * 4;
        bp[r] = hi;
        bp[2 + r] = lo;
    }
    // ---- stage B heads (single tf32) ----
    for (int e = tid; e < 96 * 72; e += NTH) {
        int jj = e / 72, k = e % 72;
        float v = 0.f;
        if (k < 64) {
            if (jj < 16)      v = Wpi[jj * 64 + k];
            else if (jj < 48) v = Wmu[(jj - 16) * 64 + k];
            else if (jj < 80) v = Wls[(jj - 48) * 64 + k];
            else              v = Wcorr[(jj - 80) * 64 + k];
        } else if (k == 66) {
            if (jj < 16)      v = bpi[jj];
            else if (jj < 48) v = bmu[jj - 16];
            else if (jj < 80) v = bls[jj - 48];
            else              v = bcorr[jj - 80];
        }
        int nt = jj >> 3, kt = k >> 3, kl = k & 7;
        int lanep = (jj & 7) * 4 + (kl & 3);
        int r = kl >> 2;
        smu[SM_BHD + ((nt * 9 + kt) * 32 + lanep) * 2 + r] = f2tf(v);
    }
    __syncthreads();   // A zero done before A staging writes below

    // ---- stage A: h0 (hi+lo) ----
    for (int e = tid; e < 32 * 64; e += NTH) {
        int s = e >> 6, k = e & 63;
        float v = g_h0[(nb + s) * 64 + k];
        uint32_t hi = f2tf(v);
        uint32_t lo = f2tf(v - __uint_as_float(hi));
        int kt = k >> 3, mt = s >> 4;
        int lanep = (s & 7) * 4 + (k & 3);
        int r = ((s >> 3) & 1) + 2 * ((k >> 2) & 1);
        int fi = ((kt * 2 + mt) * 32 + lanep) * 4 + r;
        smu[SM_AH + fi] = hi;
        smu[SM_AL + fi] = lo;
    }
    // ---- stage A: d0 = tgt_present, const 1 ----
    if (tid < 32) {
        int s = tid;
        int b = (nb + s) & (BSZ - 1);
        float dx = inp_seqs[(b * 8 + 7) * 24 + 20];
        float dy = inp_seqs[(b * 8 + 7) * 24 + 21];
        int mt = s >> 4, rh = (s >> 3) & 1;
        int base = ((16 + mt) * 32 + (s & 7) * 4);
        uint32_t hx = f2tf(dx), hy = f2tf(dy);
        smu[SM_AH + (base + 0) * 4 + rh] = hx;
        smu[SM_AL + (base + 0) * 4 + rh] = f2tf(dx - __uint_as_float(hx));
        smu[SM_AH + (base + 1) * 4 + rh] = hy;
        smu[SM_AL + (base + 1) * 4 + rh] = f2tf(dy - __uint_as_float(hy));
        smu[SM_AH + (base + 2) * 4 + rh] = f2tf(1.0f);   // col 66 (bias lane)
    }

    // ---- register state: G0 + c for 4 seqs x 2 units ----
    float G0r[4][2][4];
    float c[4][2];
    #pragma unroll
    for (int j = 0; j < 4; j++) {
        int s = sr + (j & 1) * 8 + (j >> 1) * 16;
        int n = nb + s;
        #pragma unroll
        for (int dl = 0; dl < 2; dl++) {
            int u = 8 * warp + 2 * m4 + dl;
            float4 g0 = *(const float4*)(g_G0 + n * 256 + u * 4);
            G0r[j][dl][0] = g0.x; G0r[j][dl][1] = g0.y;
            G0r[j][dl][2] = g0.z; G0r[j][dl][3] = g0.w;
            c[j][dl] = g_c0[n * 64 + u];
        }
    }

    const int b_mine = (nb + lane) & (BSZ - 1);
    const int sh = lane >> 4;
    const int gc = lane & 15;
    float lacc[2] = {0.f, 0.f};

    const uint4* ahp = (const uint4*)(sm + SM_AH) + lane;
    const uint4* alp = (const uint4*)(sm + SM_AL) + lane;
    const uint4* bgp = (const uint4*)(sm + SM_BG) + (4 * warp * 9) * 32 + lane;
    const uint2* bhp = (const uint2*)(sm + SM_BHD) + (2 * warp * 9) * 32 + lane;

    __syncthreads();

    for (int t = 1; t <= TT; t++) {
        // prefetch pred row t-1 (decode for t+1 AND GMM target for t)
        float pdx = 0.f, pdy = 0.f;
        if (tid < 32) {
            const float* pr = pred_seqs + (b_mine * TT + (t - 1)) * 24 + 20;
            pdx = pr[0];
            pdy = pr[1];
        }

        // ======== gates MMA: 3-term tf32 ========
        float acc[4][2][4];
        #pragma unroll
        for (int a = 0; a < 4; a++)
            #pragma unroll
            for (int b = 0; b < 2; b++)
                #pragma unroll
                for (int r = 0; r < 4; r++) acc[a][b][r] = 0.f;

        #pragma unroll
        for (int kt = 0; kt < 9; kt++) {
            uint4 ah0 = ahp[(kt * 2 + 0) * 32];
            uint4 ah1 = ahp[(kt * 2 + 1) * 32];
            uint4 al0 = alp[(kt * 2 + 0) * 32];
            uint4 al1 = alp[(kt * 2 + 1) * 32];
            #pragma unroll
            for (int ntl = 0; ntl < 4; ntl++) {
                uint4 B4 = bgp[(ntl * 9 + kt) * 32];
                mma8(acc[ntl][0], ah0, B4.x, B4.y);
                mma8(acc[ntl][1], ah1, B4.x, B4.y);
                mma8(acc[ntl][0], ah0, B4.z, B4.w);
                mma8(acc[ntl][1], ah1, B4.z, B4.w);
                mma8(acc[ntl][0], al0, B4.x, B4.y);
                mma8(acc[ntl][1], al1, B4.x, B4.y);
            }
        }

        // ======== pointwise LSTM (registers) ========
        float hreg[4][2];
        #pragma unroll
        for (int j = 0; j < 4; j++) {
            int mt = j >> 1, rh = j & 1;
            #pragma unroll
            for (int dl = 0; dl < 2; dl++) {
                float gi = acc[2 * dl][mt][2 * rh + 0] + G0r[j][dl][0];
                float gf = acc[2 * dl][mt][2 * rh + 1] + G0r[j][dl][1];
                float gg = acc[2 * dl + 1][mt][2 * rh + 0] + G0r[j][dl][2];
                float go = acc[2 * dl + 1][mt][2 * rh + 1] + G0r[j][dl][3];
                float cc = sigg(gf) * c[j][dl] + sigg(gi) * tanhg(gg);
                c[j][dl] = cc;
                hreg[j][dl] = sigg(go) * tanhg(cc);
            }
        }
        __syncthreads();   // all A-frag reads done

        // ======== write h (hi+lo) + d(t+1) + DT stash ========
        #pragma unroll
        for (int j = 0; j < 4; j++) {
            int mt = j >> 1;
            int s = sr + (j & 1) * 8 + mt * 16;
            #pragma unroll
            for (int dl = 0; dl < 2; dl++) {
                int u = 8 * warp + 2 * m4 + dl;
                int kt = u >> 3;
                int lanep = (s & 7) * 4 + (u & 3);
                int r = ((s >> 3) & 1) + 2 * ((u >> 2) & 1);
                int fi = ((kt * 2 + mt) * 32 + lanep) * 4 + r;
                float h = hreg[j][dl];
                uint32_t hi = f2tf(h);
                smu[SM_AH + fi] = hi;
                smu[SM_AL + fi] = f2tf(h - __uint_as_float(hi));
            }
        }
        if (tid < 32) {
            int s = lane;
            sm[SM_DT + s * 2]     = pdx;
            sm[SM_DT + s * 2 + 1] = pdy;
            int mt = s >> 4, rh = (s >> 3) & 1;
            int base = ((16 + mt) * 32 + (s & 7) * 4);
            uint32_t hx = f2tf(pdx), hy = f2tf(pdy);
            smu[SM_AH + (base + 0) * 4 + rh] = hx;
            smu[SM_AL + (base + 0) * 4 + rh] = f2tf(pdx - __uint_as_float(hx));
            smu[SM_AH + (base + 1) * 4 + rh] = hy;
            smu[SM_AL + (base + 1) * 4 + rh] = f2tf(pdy - __uint_as_float(hy));
        }
        __syncthreads();   // new A + DT visible

        // ======== heads MMA (warps 0-5, single tf32) ========
        if (warp < 6) {
            float facc[2][2][4];
            #pragma unroll
            for (int a = 0; a < 2; a++)
                #pragma unroll
                for (int b = 0; b < 2; b++)
                    #pragma unroll
                    for (int r = 0; r < 4; r++) facc[a][b][r] = 0.f;
            #pragma unroll
            for (int kt = 0; kt < 9; kt++) {
                uint4 ah0 = ahp[(kt * 2 + 0) * 32];
                uint4 ah1 = ahp[(kt * 2 + 1) * 32];
                #pragma unroll
                for (int ntl = 0; ntl < 2; ntl++) {
                    uint2 Bh = bhp[(ntl * 9 + kt) * 32];
                    mma8(facc[ntl][0], ah0, Bh.x, Bh.y);
                    mma8(facc[ntl][1], ah1, Bh.x, Bh.y);
                }
            }
            #pragma unroll
            for (int ntl = 0; ntl < 2; ntl++) {
                int jc = 16 * warp + 8 * ntl + 2 * m4;
                #pragma unroll
                for (int mt = 0; mt < 2; mt++) {
                    int r0 = sr + 16 * mt;
                    *(float2*)(sm + SM_PO + r0 * 100 + jc) =
                        make_float2(facc[ntl][mt][0], facc[ntl][mt][1]);
                    *(float2*)(sm + SM_PO + (r0 + 8) * 100 + jc) =
                        make_float2(facc[ntl][mt][2], facc[ntl][mt][3]);
                }
            }
        }
        __syncthreads();   // Po visible

        // ======== GMM + LSE: warp = 4 seqs (2 passes x 2 seqs x 16 comps) ====
        #pragma unroll
        for (int it = 0; it < 2; it++) {
            int gs = 4 * warp + 2 * it + sh;
            float txv = sm[SM_DT + gs * 2];
            float tyv = sm[SM_DT + gs * 2 + 1];
            const float* pr = sm + SM_PO + gs * 100;
            float pi  = pr[gc];
            float2 mu  = *(const float2*)(pr + 16 + 2 * gc);
            float2 lsv = *(const float2*)(pr + 48 + 2 * gc);
            float corr = tanhg(pr[80 + gc]);
            float ls0 = fminf(fmaxf(lsv.x, -10.f), 10.f);
            float ls1 = fminf(fmaxf(lsv.y, -10.f), 10.f);
            float dx = txv - mu.x, dy = tyv - mu.y;
            float z0 = dx * __expf(-ls0);
            float z1 = dy * __expf(-ls1);
            float omr  = 1.f - corr * corr;
            float quad = z0 * z0 + z1 * z1 - 2.f * corr * z0 * z1;
            float cv = -1.8378770664093453f - (ls0 + ls1)
                       - 0.5f * __logf(omr) - 0.5f * __fdividef(quad, omr);
            float a = pi + cv;
            float b2 = pi;
            float ma = a, mb = b2;
            #pragma unroll
            for (int xm = 1; xm < 16; xm <<= 1) {
                ma = fmaxf(ma, __shfl_xor_sync(0xFFFFFFFFu, ma, xm));
                mb = fmaxf(mb, __shfl_xor_sync(0xFFFFFFFFu, mb, xm));
            }
            float ea = __expf(a - ma);
            float eb = __expf(b2 - mb);
            #pragma unroll
            for (int xm = 1; xm < 16; xm <<= 1) {
                ea += __shfl_xor_sync(0xFFFFFFFFu, ea, xm);
                eb += __shfl_xor_sync(0xFFFFFFFFu, eb, xm);
            }
            float lp = (ma + __logf(ea)) - (mb + __logf(eb));
            lacc[it] += fminf(lp, 50.f);
        }
        // no trailing barrier: DT/Po rewritten only after next step's sync #1/#2
    }

    if ((lane & 15) == 0) {
        out[nb + 4 * warp + 0 + sh] = lacc[0];
        out[nb + 4 * warp + 2 + sh] = lacc[1];
    }
}

// ---------------------------------------------------------------------------
extern "C" void kernel_launch(void* const* d_in, const int* in_sizes, int n_in,
                              void* d_out, int out_size)
{
    const float* x      = (const float*)d_in[0];
    const float* z      = (const float*)d_in[1];
    const float* inps   = (const float*)d_in[2];
    const float* preds  = (const float*)d_in[3];
    const float* Wh0    = (const float*)d_in[4];
    const float* bh0    = (const float*)d_in[5];
    const float* Wc0    = (const float*)d_in[6];
    const float* bc0    = (const float*)d_in[7];
    const float* Wih    = (const float*)d_in[8];
    const float* Whh    = (const float*)d_in[9];
    const float* bih    = (const float*)d_in[10];
    const float* bhh    = (const float*)d_in[11];
    const float* Wpi    = (const float*)d_in[12];
    const float* bpi    = (const float*)d_in[13];
    const float* Wmu    = (const float*)d_in[14];
    const float* bmu    = (const float*)d_in[15];
    const float* Wls    = (const float*)d_in[16];
    const float* bls    = (const float*)d_in[17];
    const float* Wcorr  = (const float*)d_in[18];
    const float* bcorr  = (const float*)d_in[19];
    float* out = (float*)d_out;

    cudaFuncSetAttribute(phase2_kernel,
                         cudaFuncAttributeMaxDynamicSharedMemorySize, SMEM_BYTES);

    dim3 g1(NSEQ / 64, 384 / 64);
    phase1_kernel<<<g1, 256>>>(x, z, Wih, Wh0, Wc0, bih, bhh, bh0, bc0);

    phase2_kernel<<<NSEQ / 32, NTH, SMEM_BYTES>>>(
        inps, preds, Whh, Wih,
        Wpi, bpi, Wmu, bmu, Wls, bls, Wcorr, bcorr, out);
}